// round 8
// baseline (speedup 1.0000x reference)
#include <cuda_runtime.h>
#include <cuda_bf16.h>
#include <cstdint>

#define BATCH 4
#define NTOK  2048
#define EDIM  1024
#define DDIM  64
#define QTILE 64
#define NQT   (NTOK / QTILE)
#define CHUNK 8
#define NCH   4

// ---- pre-converted split-bf16 tensors (written by proj, read by attn) ------
__device__ __align__(16) uint16_t g_qh[BATCH * NTOK * DDIM];   // q hi, x0.125
__device__ __align__(16) uint16_t g_ql[BATCH * NTOK * DDIM];   // q lo
__device__ __align__(16) uint16_t g_kTh[BATCH * DDIM * NTOK];  // k hi, [e][tok]
__device__ __align__(16) uint16_t g_kTl[BATCH * DDIM * NTOK];
__device__ __align__(16) uint16_t g_vh[BATCH * NTOK * DDIM];   // v hi, [tok][d]
__device__ __align__(16) uint16_t g_vl[BATCH * NTOK * DDIM];
// pre-split weights: [proj 3][e 1024][n 64] bf16 hi/lo
__device__ __align__(16) uint16_t g_wh[3 * EDIM * DDIM];
__device__ __align__(16) uint16_t g_wl[3 * EDIM * DDIM];
// split-K partials
__device__ float g_pO[BATCH * NQT * NCH * QTILE * QTILE];
__device__ float g_pm[BATCH * NQT * NCH * QTILE];
__device__ float g_pl[BATCH * NQT * NCH * QTILE];

// ======================= helpers ============================================
__device__ __forceinline__ uint32_t smem_u32(const void* p) {
    uint32_t a;
    asm("{ .reg .u64 t; cvta.to.shared.u64 t, %1; cvt.u32.u64 %0, t; }"
        : "=r"(a) : "l"(p));
    return a;
}
#define SWZ(off) ((off) ^ (((off) >> 3) & 0x70))

__device__ __forceinline__ uint32_t pk_bf(float lo, float hi) {
    uint32_t r;
    asm("cvt.rn.bf16x2.f32 %0, %1, %2;" : "=r"(r) : "f"(hi), "f"(lo));
    return r;
}
__device__ __forceinline__ float bf2f(uint16_t b) {
    return __uint_as_float(((uint32_t)b) << 16);
}
__device__ __forceinline__ uint16_t bfbits(float x) {
    return __bfloat16_as_ushort(__float2bfloat16(x));
}
__device__ __forceinline__ void split2(float a, float b, uint32_t& h, uint32_t& l) {
    float ha = bf2f(bfbits(a));
    float hb = bf2f(bfbits(b));
    h = pk_bf(ha, hb);
    l = pk_bf(a - ha, b - hb);
}
__device__ __forceinline__ void ldmx4(uint32_t a, uint32_t r[4]) {
    asm volatile("ldmatrix.sync.aligned.m8n8.x4.shared.b16 {%0,%1,%2,%3}, [%4];"
        : "=r"(r[0]), "=r"(r[1]), "=r"(r[2]), "=r"(r[3]) : "r"(a));
}
__device__ __forceinline__ void ldmx4t(uint32_t a, uint32_t r[4]) {
    asm volatile("ldmatrix.sync.aligned.m8n8.x4.trans.shared.b16 {%0,%1,%2,%3}, [%4];"
        : "=r"(r[0]), "=r"(r[1]), "=r"(r[2]), "=r"(r[3]) : "r"(a));
}
__device__ __forceinline__ void mma_bf16(float c[4], const uint32_t a[4],
                                         uint32_t b0, uint32_t b1) {
    asm volatile(
        "mma.sync.aligned.m16n8k16.row.col.f32.bf16.bf16.f32 "
        "{%0,%1,%2,%3}, {%4,%5,%6,%7}, {%8,%9}, {%0,%1,%2,%3};"
        : "+f"(c[0]), "+f"(c[1]), "+f"(c[2]), "+f"(c[3])
        : "r"(a[0]), "r"(a[1]), "r"(a[2]), "r"(a[3]), "r"(b0), "r"(b1));
}

// ======================= W pre-split ========================================
__global__ __launch_bounds__(256) void wsplit(
    const float* __restrict__ Wq, const float* __restrict__ Wk,
    const float* __restrict__ Wv)
{
    const int f = blockIdx.x * 256 + threadIdx.x;   // float4 index, 49152 total
    const int p = f >> 14;                          // 16384 float4 per W
    const int rem = f & 16383;
    const float* W = (p == 0) ? Wq : (p == 1) ? Wk : Wv;
    float4 v = ((const float4*)W)[rem];
    uint32_t h0, l0, h1, l1;
    split2(v.x, v.y, h0, l0);
    split2(v.z, v.w, h1, l1);
    const size_t o = ((size_t)p << 16) + (size_t)rem * 4;   // element offset
    *(uint2*)(g_wh + o) = make_uint2(h0, h1);
    *(uint2*)(g_wl + o) = make_uint2(l0, l1);
}

// ======================= HMMA projection (double-buffered) ==================
#define PJ_M   128
#define PJ_KC  64
#define PJ_NST (EDIM / PJ_KC)
// per-buffer offsets
#define OFF_AH 0
#define OFF_AL (OFF_AH + PJ_M * 128)      // 16384
#define OFF_BH (OFF_AL + PJ_M * 128)      // 32768
#define OFF_BL (OFF_BH + PJ_KC * 128)     // 40960
#define BUFSZ  (OFF_BL + PJ_KC * 128)     // 49152
#define PJ_SMEM (2 * BUFSZ)               // 98304

__global__ __launch_bounds__(256, 2) void proj_tc(
    const float* __restrict__ Kin, const float* __restrict__ Qin,
    const float* __restrict__ Vin)
{
    extern __shared__ char psm[];
    const uint32_t sb = smem_u32(psm);
    const int tid  = threadIdx.x;
    const int wid  = tid >> 5;
    const int lane = tid & 31;
    const int p    = blockIdx.y;

    const float* X = (p == 0) ? Qin : (p == 1) ? Kin : Vin;
    const uint16_t* WH = g_wh + ((size_t)p << 16);
    const uint16_t* WL = g_wl + ((size_t)p << 16);
    const int row0 = blockIdx.x * PJ_M;

    const int warp_m = (wid & 3) * 32;
    const int warp_n = (wid >> 2) * 32;

    // conversion/copy roles
    const int ar = tid >> 1;             // A row 0..127
    const int ah = tid & 1;              // col half (32 cols)
    const int b0r = tid >> 3, b0c = tid & 7;          // B rows 0..31
    const int b1r = (tid + 256) >> 3, b1c = tid & 7;  // B rows 32..63

    float acc[2][4][4];
    #pragma unroll
    for (int mt = 0; mt < 2; mt++)
        #pragma unroll
        for (int j = 0; j < 4; j++)
            #pragma unroll
            for (int r = 0; r < 4; r++) acc[mt][j][r] = 0.f;

    float4 xa[8];
    uint4 wbh[2], wbl[2];

    // ---- preload + convert stage 0 into buffer 0 ----
    {
        const float4* xp = (const float4*)(X + (size_t)(row0 + ar) * EDIM + ah * 32);
        #pragma unroll
        for (int i = 0; i < 8; i++) xa[i] = xp[i];
        wbh[0] = *(const uint4*)(WH + (size_t)b0r * DDIM + b0c * 8);
        wbh[1] = *(const uint4*)(WH + (size_t)b1r * DDIM + b1c * 8);
        wbl[0] = *(const uint4*)(WL + (size_t)b0r * DDIM + b0c * 8);
        wbl[1] = *(const uint4*)(WL + (size_t)b1r * DDIM + b1c * 8);

        #pragma unroll
        for (int i = 0; i < 4; i++) {
            float4 pp = xa[2 * i], qq = xa[2 * i + 1];
            uint32_t h0, l0, h1, l1, h2, l2, h3, l3;
            split2(pp.x, pp.y, h0, l0); split2(pp.z, pp.w, h1, l1);
            split2(qq.x, qq.y, h2, l2); split2(qq.z, qq.w, h3, l3);
            uint32_t off = (uint32_t)(ar * 128 + ah * 64 + i * 16);
            *(uint4*)(psm + OFF_AH + SWZ(off)) = make_uint4(h0, h1, h2, h3);
            *(uint4*)(psm + OFF_AL + SWZ(off)) = make_uint4(l0, l1, l2, l3);
        }
        uint32_t o0 = (uint32_t)((b0r & 63) * 128 + b0c * 16);
        uint32_t o1 = (uint32_t)((b1r & 63) * 128 + b1c * 16);
        *(uint4*)(psm + OFF_BH + SWZ(o0)) = wbh[0];
        *(uint4*)(psm + OFF_BH + SWZ(o1)) = wbh[1];
        *(uint4*)(psm + OFF_BL + SWZ(o0)) = wbl[0];
        *(uint4*)(psm + OFF_BL + SWZ(o1)) = wbl[1];
    }
    __syncthreads();

    for (int s = 0; s < PJ_NST; s++) {
        const int cur = s & 1;
        const int nxt = cur ^ 1;
        char* nxtb = psm + nxt * BUFSZ;
        const uint32_t curs = sb + cur * BUFSZ;

        // ---- issue LDGs for stage s+1 (consumed after MMA phase) ----
        const bool more = (s + 1 < PJ_NST);
        if (more) {
            const float4* xp = (const float4*)(X + (size_t)(row0 + ar) * EDIM
                                               + (s + 1) * PJ_KC + ah * 32);
            #pragma unroll
            for (int i = 0; i < 8; i++) xa[i] = xp[i];
            const size_t wo = (size_t)(s + 1) * PJ_KC * DDIM;
            wbh[0] = *(const uint4*)(WH + wo + (size_t)b0r * DDIM + b0c * 8);
            wbh[1] = *(const uint4*)(WH + wo + (size_t)b1r * DDIM + b1c * 8);
            wbl[0] = *(const uint4*)(WL + wo + (size_t)b0r * DDIM + b0c * 8);
            wbl[1] = *(const uint4*)(WL + wo + (size_t)b1r * DDIM + b1c * 8);
        }

        // ---- MMA on current buffer ----
        #pragma unroll
        for (int kk = 0; kk < 4; kk++) {
            uint32_t bh[2][4], bl[2][4];
            #pragma unroll
            for (int nt = 0; nt < 2; nt++) {
                uint32_t off = (uint32_t)((kk * 16 + (lane & 15)) * 128
                             + (warp_n + nt * 16) * 2 + (lane >> 4) * 16);
                ldmx4t(curs + OFF_BH + SWZ(off), bh[nt]);
                ldmx4t(curs + OFF_BL + SWZ(off), bl[nt]);
            }
            #pragma unroll
            for (int mt = 0; mt < 2; mt++) {
                uint32_t afh[4], afl[4];
                uint32_t off = (uint32_t)((warp_m + mt * 16 + (lane & 15)) * 128
                             + kk * 32 + (lane >> 4) * 16);
                ldmx4(curs + OFF_AH + SWZ(off), afh);
                ldmx4(curs + OFF_AL + SWZ(off), afl);
                #pragma unroll
                for (int nt = 0; nt < 2; nt++) {
                    #pragma unroll
                    for (int j = 0; j < 2; j++) {
                        float* cc = acc[mt][nt * 2 + j];
                        uint32_t h0 = bh[nt][j * 2], h1 = bh[nt][j * 2 + 1];
                        uint32_t l0 = bl[nt][j * 2], l1 = bl[nt][j * 2 + 1];
                        mma_bf16(cc, afh, h0, h1);
                        mma_bf16(cc, afh, l0, l1);
                        mma_bf16(cc, afl, h0, h1);
                    }
                }
            }
        }

        // ---- convert + store stage s+1 into next buffer ----
        if (more) {
            #pragma unroll
            for (int i = 0; i < 4; i++) {
                float4 pp = xa[2 * i], qq = xa[2 * i + 1];
                uint32_t h0, l0, h1, l1, h2, l2, h3, l3;
                split2(pp.x, pp.y, h0, l0); split2(pp.z, pp.w, h1, l1);
                split2(qq.x, qq.y, h2, l2); split2(qq.z, qq.w, h3, l3);
                uint32_t off = (uint32_t)(ar * 128 + ah * 64 + i * 16);
                *(uint4*)(nxtb + OFF_AH + SWZ(off)) = make_uint4(h0, h1, h2, h3);
                *(uint4*)(nxtb + OFF_AL + SWZ(off)) = make_uint4(l0, l1, l2, l3);
            }
            uint32_t o0 = (uint32_t)((b0r & 63) * 128 + b0c * 16);
            uint32_t o1 = (uint32_t)((b1r & 63) * 128 + b1c * 16);
            *(uint4*)(nxtb + OFF_BH + SWZ(o0)) = wbh[0];
            *(uint4*)(nxtb + OFF_BH + SWZ(o1)) = wbh[1];
            *(uint4*)(nxtb + OFF_BL + SWZ(o0)) = wbl[0];
            *(uint4*)(nxtb + OFF_BL + SWZ(o1)) = wbl[1];
        }
        __syncthreads();
    }

    // ---- epilogue: emit split-bf16 ----
    const int mrow = lane >> 2;
    const int ncol = (lane & 3) * 2;

    if (p != 1) {
        const float scl = (p == 0) ? 0.125f : 1.0f;
        uint16_t* GH = (p == 0) ? g_qh : g_vh;
        uint16_t* GL = (p == 0) ? g_ql : g_vl;
        #pragma unroll
        for (int mt = 0; mt < 2; mt++) {
            #pragma unroll
            for (int j = 0; j < 4; j++) {
                const float* cc = acc[mt][j];
                int gm = row0 + warp_m + mt * 16 + mrow;
                int gn = warp_n + j * 8 + ncol;
                uint32_t h, l;
                split2(cc[0] * scl, cc[1] * scl, h, l);
                *(uint32_t*)(GH + (size_t)gm * DDIM + gn) = h;
                *(uint32_t*)(GL + (size_t)gm * DDIM + gn) = l;
                split2(cc[2] * scl, cc[3] * scl, h, l);
                *(uint32_t*)(GH + (size_t)(gm + 8) * DDIM + gn) = h;
                *(uint32_t*)(GL + (size_t)(gm + 8) * DDIM + gn) = l;
            }
        }
    } else {
        __syncthreads();
        uint16_t* kh_s = (uint16_t*)psm;          // [64 e][128 tok]
        uint16_t* kl_s = kh_s + 64 * 128;
        #pragma unroll
        for (int mt = 0; mt < 2; mt++) {
            #pragma unroll
            for (int j = 0; j < 4; j++) {
                const float* cc = acc[mt][j];
                int tok = warp_m + mt * 16 + mrow;
                int e   = warp_n + j * 8 + ncol;
                #pragma unroll
                for (int r = 0; r < 2; r++) {
                    float c0 = cc[r * 2], c1 = cc[r * 2 + 1];
                    int tk = tok + r * 8;
                    uint16_t h0 = bfbits(c0), h1 = bfbits(c1);
                    kh_s[e * 128 + tk]       = h0;
                    kh_s[(e + 1) * 128 + tk] = h1;
                    kl_s[e * 128 + tk]       = bfbits(c0 - bf2f(h0));
                    kl_s[(e + 1) * 128 + tk] = bfbits(c1 - bf2f(h1));
                }
            }
        }
        __syncthreads();
        const int bb   = row0 >> 11;
        const int tok0 = row0 & 2047;
        #pragma unroll
        for (int t = 0; t < 4; t++) {
            int f = tid + t * 256;
            int row = f >> 4, cch = f & 15;
            *(uint4*)(g_kTh + ((size_t)(bb * DDIM + row)) * NTOK + tok0 + cch * 8) =
                *(const uint4*)(kh_s + row * 128 + cch * 8);
            *(uint4*)(g_kTl + ((size_t)(bb * DDIM + row)) * NTOK + tok0 + cch * 8) =
                *(const uint4*)(kl_s + row * 128 + cch * 8);
        }
    }
}

// ======================= HMMA split-K flash attention =======================
#define AOFF_QH 0
#define AOFF_QL (AOFF_QH + 64 * 128)
#define AOFF_KH (AOFF_QL + 64 * 128)
#define AOFF_KL (AOFF_KH + 64 * 128)
#define AOFF_VH (AOFF_KL + 64 * 128)
#define AOFF_VL (AOFF_VH + 64 * 128)
#define ATTN_SMEM (AOFF_VL + 64 * 128)    // 49152

__global__ __launch_bounds__(128) void attn_part(void)
{
    extern __shared__ char smc[];
    const uint32_t sb = smem_u32(smc);

    const int b   = blockIdx.y;
    const int qt  = NQT - 1 - (int)blockIdx.x;
    const int ch  = blockIdx.z;
    const int kt0 = ch * CHUNK;
    if (kt0 > qt) return;
    const int ktEnd = min(qt + 1, kt0 + CHUNK);
    const int q0 = qt * QTILE;

    const int tid = threadIdx.x;
    const int wid = tid >> 5;
    const int lane = tid & 31;
    const int warp_m = wid * 16;
    const int rA = lane >> 2;

    {
        const uint16_t* QH = g_qh + ((size_t)b * NTOK + q0) * DDIM;
        const uint16_t* QL = g_ql + ((size_t)b * NTOK + q0) * DDIM;
        #pragma unroll
        for (int t = 0; t < 4; t++) {
            int f = tid + t * 128;
            int row = f >> 3, c = f & 7;
            uint32_t off = (uint32_t)(row * 128 + c * 16);
            *(uint4*)(smc + AOFF_QH + SWZ(off)) = *(const uint4*)(QH + row * 64 + c * 8);
            *(uint4*)(smc + AOFF_QL + SWZ(off)) = *(const uint4*)(QL + row * 64 + c * 8);
        }
    }
    __syncthreads();

    uint32_t qfh[4][4], qfl[4][4];
    #pragma unroll
    for (int kk = 0; kk < 4; kk++) {
        uint32_t off = (uint32_t)((warp_m + (lane & 15)) * 128 + kk * 32 + (lane >> 4) * 16);
        ldmx4(sb + AOFF_QH + SWZ(off), qfh[kk]);
        ldmx4(sb + AOFF_QL + SWZ(off), qfl[kk]);
    }

    float m2[2] = { -1e30f, -1e30f };
    float l2[2] = { 0.f, 0.f };
    float o[8][4];
    #pragma unroll
    for (int t = 0; t < 8; t++)
        #pragma unroll
        for (int r = 0; r < 4; r++) o[t][r] = 0.f;

    const uint16_t* KH = g_kTh + (size_t)b * DDIM * NTOK;
    const uint16_t* KL = g_kTl + (size_t)b * DDIM * NTOK;
    const uint16_t* VH = g_vh + (size_t)b * NTOK * DDIM;
    const uint16_t* VL = g_vl + (size_t)b * NTOK * DDIM;

    for (int kt = kt0; kt < ktEnd; kt++) {
        const int k0 = kt * QTILE;
        __syncthreads();
        #pragma unroll
        for (int t = 0; t < 4; t++) {
            int f = tid + t * 128;
            int row = f >> 3, c = f & 7;
            uint32_t off = (uint32_t)(row * 128 + c * 16);
            *(uint4*)(smc + AOFF_KH + SWZ(off)) =
                *(const uint4*)(KH + (size_t)row * NTOK + k0 + c * 8);
            *(uint4*)(smc + AOFF_KL + SWZ(off)) =
                *(const uint4*)(KL + (size_t)row * NTOK + k0 + c * 8);
            *(uint4*)(smc + AOFF_VH + SWZ(off)) =
                *(const uint4*)(VH + (size_t)(k0 + row) * DDIM + c * 8);
            *(uint4*)(smc + AOFF_VL + SWZ(off)) =
                *(const uint4*)(VL + (size_t)(k0 + row) * DDIM + c * 8);
        }
        __syncthreads();

        float s[8][4];
        #pragma unroll
        for (int t = 0; t < 8; t++)
            #pragma unroll
            for (int r = 0; r < 4; r++) s[t][r] = 0.f;

        #pragma unroll
        for (int kk = 0; kk < 4; kk++) {
            #pragma unroll
            for (int g = 0; g < 4; g++) {
                uint32_t off = (uint32_t)((kk * 16 + (lane & 15)) * 128
                             + g * 32 + (lane >> 4) * 16);
                uint32_t bh[4], bl[4];
                ldmx4t(sb + AOFF_KH + SWZ(off), bh);
                ldmx4t(sb + AOFF_KL + SWZ(off), bl);
                #pragma unroll
                for (int j = 0; j < 2; j++) {
                    float* cc = s[g * 2 + j];
                    mma_bf16(cc, qfh[kk], bh[j * 2], bh[j * 2 + 1]);
                    mma_bf16(cc, qfh[kk], bl[j * 2], bl[j * 2 + 1]);
                    mma_bf16(cc, qfl[kk], bh[j * 2], bh[j * 2 + 1]);
                }
            }
        }

        if (kt == qt) {
            const int rgA = q0 + warp_m + rA;
            const int rgB = rgA + 8;
            #pragma unroll
            for (int t = 0; t < 8; t++) {
                int gc = k0 + t * 8 + (lane & 3) * 2;
                if (gc > rgA)     s[t][0] = -1e30f;
                if (gc + 1 > rgA) s[t][1] = -1e30f;
                if (gc > rgB)     s[t][2] = -1e30f;
                if (gc + 1 > rgB) s[t][3] = -1e30f;
            }
        }

        float mxA = -1e30f, mxB = -1e30f;
        #pragma unroll
        for (int t = 0; t < 8; t++) {
            mxA = fmaxf(mxA, fmaxf(s[t][0], s[t][1]));
            mxB = fmaxf(mxB, fmaxf(s[t][2], s[t][3]));
        }
        mxA = fmaxf(mxA, __shfl_xor_sync(0xffffffffu, mxA, 1));
        mxA = fmaxf(mxA, __shfl_xor_sync(0xffffffffu, mxA, 2));
        mxB = fmaxf(mxB, __shfl_xor_sync(0xffffffffu, mxB, 1));
        mxB = fmaxf(mxB, __shfl_xor_sync(0xffffffffu, mxB, 2));
        const float nmA = fmaxf(m2[0], mxA);
        const float nmB = fmaxf(m2[1], mxB);
        const float aA = __expf(m2[0] - nmA);
        const float aB = __expf(m2[1] - nmB);
        float rsA = 0.f, rsB = 0.f;
        #pragma unroll
        for (int t = 0; t < 8; t++) {
            s[t][0] = __expf(s[t][0] - nmA);
            s[t][1] = __expf(s[t][1] - nmA);
            s[t][2] = __expf(s[t][2] - nmB);
            s[t][3] = __expf(s[t][3] - nmB);
            rsA += s[t][0] + s[t][1];
            rsB += s[t][2] + s[t][3];
        }
        rsA += __shfl_xor_sync(0xffffffffu, rsA, 1);
        rsA += __shfl_xor_sync(0xffffffffu, rsA, 2);
        rsB += __shfl_xor_sync(0xffffffffu, rsB, 1);
        rsB += __shfl_xor_sync(0xffffffffu, rsB, 2);
        l2[0] = l2[0] * aA + rsA;  m2[0] = nmA;
        l2[1] = l2[1] * aB + rsB;  m2[1] = nmB;
        #pragma unroll
        for (int t = 0; t < 8; t++) {
            o[t][0] *= aA; o[t][1] *= aA;
            o[t][2] *= aB; o[t][3] *= aB;
        }

        #pragma unroll
        for (int kk = 0; kk < 4; kk++) {
            uint32_t ph[4], pl[4];
            split2(s[2 * kk][0],     s[2 * kk][1],     ph[0], pl[0]);
            split2(s[2 * kk][2],     s[2 * kk][3],     ph[1], pl[1]);
            split2(s[2 * kk + 1][0], s[2 * kk + 1][1], ph[2], pl[2]);
            split2(s[2 * kk + 1][2], s[2 * kk + 1][3], ph[3], pl[3]);
            #pragma unroll
            for (int g = 0; g < 4; g++) {
                uint32_t off = (uint32_t)((kk * 16 + (lane & 15)) * 128
                             + g * 32 + (lane >> 4) * 16);
                uint32_t vh[4], vl[4];
                ldmx4t(sb + AOFF_VH + SWZ(off), vh);
                ldmx4t(sb + AOFF_VL + SWZ(off), vl);
                #pragma unroll
                for (int j = 0; j < 2; j++) {
                    float* cc = o[g * 2 + j];
                    mma_bf16(cc, ph, vh[j * 2], vh[j * 2 + 1]);
                    mma_bf16(cc, ph, vl[j * 2], vl[j * 2 + 1]);
                    mma_bf16(cc, pl, vh[j * 2], vh[j * 2 + 1]);
                }
            }
        }
    }

    const int tb = (b * NQT + qt) * NCH + ch;
    float* po = g_pO + (size_t)tb * (QTILE * QTILE);
    #pragma unroll
    for (int t = 0; t < 8; t++) {
        int gn = t * 8 + (lane & 3) * 2;
        *(float2*)&po[(warp_m + rA) * QTILE + gn]     = make_float2(o[t][0], o[t][1]);
        *(float2*)&po[(warp_m + rA + 8) * QTILE + gn] = make_float2(o[t][2], o[t][3]);
    }
    if ((lane & 3) == 0) {
        g_pm[tb * QTILE + warp_m + rA]     = m2[0];
        g_pm[tb * QTILE + warp_m + rA + 8] = m2[1];
        g_pl[tb * QTILE + warp_m + rA]     = l2[0];
        g_pl[tb * QTILE + warp_m + rA + 8] = l2[1];
    }
}

// ======================= merge ==============================================
__global__ __launch_bounds__(256) void attn_merge(float* __restrict__ out)
{
    const int qt = blockIdx.x;
    const int b  = blockIdx.y;
    const int nc = qt / CHUNK + 1;

    const int tid = threadIdx.x;
    const int r  = tid & 63;
    const int cs = tid >> 6;

    const int tb0 = (b * NQT + qt) * NCH;

    float mm[NCH], sc[NCH];
    float mstar = -1e30f;
    for (int c = 0; c < nc; c++) {
        mm[c] = g_pm[(tb0 + c) * QTILE + r];
        mstar = fmaxf(mstar, mm[c]);
    }
    float lstar = 0.f;
    for (int c = 0; c < nc; c++) {
        sc[c] = __expf(mm[c] - mstar);
        lstar += sc[c] * g_pl[(tb0 + c) * QTILE + r];
    }
    const float inv = 1.f / lstar;

    #pragma unroll
    for (int v = 0; v < 4; v++) {
        int col = cs * 16 + v * 4;
        float4 a = make_float4(0.f, 0.f, 0.f, 0.f);
        for (int c = 0; c < nc; c++) {
            const float4 p = *(const float4*)
                &g_pO[(size_t)(tb0 + c) * (QTILE * QTILE) + r * QTILE + col];
            a.x += sc[c] * p.x; a.y += sc[c] * p.y;
            a.z += sc[c] * p.z; a.w += sc[c] * p.w;
        }
        a.x *= inv; a.y *= inv; a.z *= inv; a.w *= inv;
        *(float4*)&out[((size_t)b * NTOK + qt * QTILE + r) * DDIM + col] = a;
    }
}

// ---------------------------------------------------------------------------
extern "C" void kernel_launch(void* const* d_in, const int* in_sizes, int n_in,
                              void* d_out, int out_size)
{
    (void)in_sizes; (void)n_in; (void)out_size;
    const float* K  = (const float*)d_in[0];
    const float* Q  = (const float*)d_in[1];
    const float* V  = (const float*)d_in[2];
    const float* Wk = (const float*)d_in[3];
    const float* Wq = (const float*)d_in[4];
    const float* Wv = (const float*)d_in[5];
    float* out = (float*)d_out;

    cudaFuncSetAttribute(proj_tc,   cudaFuncAttributeMaxDynamicSharedMemorySize, PJ_SMEM);
    cudaFuncSetAttribute(attn_part, cudaFuncAttributeMaxDynamicSharedMemorySize, ATTN_SMEM);

    wsplit<<<192, 256>>>(Wq, Wk, Wv);
    proj_tc<<<dim3(64, 3), 256, PJ_SMEM>>>(K, Q, V);
    attn_part<<<dim3(NQT, BATCH, NCH), 128, ATTN_SMEM>>>();
    attn_merge<<<dim3(NQT, BATCH), 256>>>(out);
}